// round 15
// baseline (speedup 1.0000x reference)
#include <cuda_runtime.h>
#include <cuda_bf16.h>
#include <cuda_fp16.h>
#include <math.h>
#include <stdint.h>

// Problem constants
#define Bb 128
#define Tt 32
#define Ee 512
#define Hh 512
#define Ll 256
#define Vv 16000

#define NCH_G  60      // gates: K2=3840 (folded bf16)
#define NCH_PQ 48      // pq: K2=3072 (folded bf16)
#define QROWS  192
#define QCH    12      // qx chunks of 64 over K=768 (fp16 single)
#define REC_CTAS 64
#define QX_CTAS  84

// Output layout: p_mus, p_sigmas, q_mus, q_sigmas, q_xs
#define OFF_PMU  ((size_t)0)
#define OFF_PSIG ((size_t)Tt * Bb * Ll)
#define OFF_QMU  ((size_t)2 * Tt * Bb * Ll)
#define OFF_QSIG ((size_t)3 * Tt * Bb * Ll)
#define OFF_QX   ((size_t)4 * Tt * Bb * Ll)

// ---------------- device scratch ----------------
__device__ float g_emb[Tt * Bb * Ee];
__device__ float g_bsum[4 * Hh];
__device__ float g_bias_pq[1024];
__device__ float g_c[Bb * Hh];
__device__ float g_pqp[8][Bb * 1024];
__device__ float g_gp[4][Bb * 2048];
__device__ int g_ctrP;
__device__ int g_bar3[Tt][3];            // rec internal barriers (3 per step)
__device__ int g_flagZ[Tt];              // z-images ready (==64)
__device__ int g_flagQ[Tt];              // qx GEMM+partials done (==84)
__device__ float g_smax[2][Bb][QX_CTAS]; // softmax partial max per (row, tile)
__device__ float g_ssum[2][Bb][QX_CTAS]; // softmax partial sumexp

// Weight images (once)
__device__ __align__(16) __nv_bfloat16 gBg[(size_t)16 * NCH_G * 8192];
__device__ __align__(16) __nv_bfloat16 gBpq[(size_t)8 * NCH_PQ * 8192];
__device__ __align__(16) __half gBqx[(size_t)QX_CTAS * QCH * QROWS * 64];   // fp16 single
// A images: pq/gates folded bf16 single; qx fp16 triple-buffered
__device__ __align__(16) __nv_bfloat16 gAg[NCH_G * 8192];
__device__ __align__(16) __nv_bfloat16 gApq[NCH_PQ * 8192];
__device__ __align__(16) __half gAqx3[3][QCH * 8192];

__device__ __forceinline__ float sigf(float x) { return 1.0f / (1.0f + expf(-x)); }

__device__ __forceinline__ uint32_t s2u(const void* p) {
    uint32_t a;
    asm("{ .reg .u64 t; cvta.to.shared.u64 t, %1; cvt.u32.u64 %0, t; }" : "=r"(a) : "l"(p));
    return a;
}
__device__ __forceinline__ void cpasync16(uint32_t dst, const void* src) {
    asm volatile("cp.async.cg.shared.global [%0], [%1], 16;"
                 :: "r"(dst), "l"(__cvta_generic_to_global(src)) : "memory");
}
__device__ __forceinline__ void ldmatrix_x4(uint32_t* r, uint32_t addr) {
    asm volatile("ldmatrix.sync.aligned.m8n8.x4.shared.b16 {%0,%1,%2,%3}, [%4];"
                 : "=r"(r[0]), "=r"(r[1]), "=r"(r[2]), "=r"(r[3]) : "r"(addr));
}
__device__ __forceinline__ void mma_bf16(float* c, const uint32_t* a, uint32_t b0, uint32_t b1) {
    asm volatile(
        "mma.sync.aligned.m16n8k16.row.col.f32.bf16.bf16.f32 "
        "{%0,%1,%2,%3}, {%4,%5,%6,%7}, {%8,%9}, {%0,%1,%2,%3};"
        : "+f"(c[0]), "+f"(c[1]), "+f"(c[2]), "+f"(c[3])
        : "r"(a[0]), "r"(a[1]), "r"(a[2]), "r"(a[3]), "r"(b0), "r"(b1));
}
__device__ __forceinline__ void mma_f16(float* c, const uint32_t* a, uint32_t b0, uint32_t b1) {
    asm volatile(
        "mma.sync.aligned.m16n8k16.row.col.f32.f16.f16.f32 "
        "{%0,%1,%2,%3}, {%4,%5,%6,%7}, {%8,%9}, {%0,%1,%2,%3};"
        : "+f"(c[0]), "+f"(c[1]), "+f"(c[2]), "+f"(c[3])
        : "r"(a[0]), "r"(a[1]), "r"(a[2]), "r"(a[3]), "r"(b0), "r"(b1));
}
__device__ __forceinline__ size_t ipos(int k2, int m) {      // bf16 folded images
    return (((size_t)(k2 >> 6) * 128 + m) << 6) + (k2 & 63);
}
__device__ __forceinline__ size_t qpos16(int k, int m) {     // fp16 qx A image
    return (size_t)(k >> 6) * 8192 + m * 64 + (k & 63);
}
__device__ __forceinline__ unsigned long long pk4(__nv_bfloat16 a, __nv_bfloat16 b,
                                                  __nv_bfloat16 c, __nv_bfloat16 d) {
    union { __nv_bfloat16 h[4]; unsigned long long u; } t;
    t.h[0] = a; t.h[1] = b; t.h[2] = c; t.h[3] = d;
    return t.u;
}
__device__ __forceinline__ void cvt4(float4 v, unsigned long long& hi, unsigned long long& lo) {
    __nv_bfloat16 h0 = __float2bfloat16(v.x), h1 = __float2bfloat16(v.y);
    __nv_bfloat16 h2 = __float2bfloat16(v.z), h3 = __float2bfloat16(v.w);
    hi = pk4(h0, h1, h2, h3);
    lo = pk4(__float2bfloat16(v.x - __bfloat162float(h0)),
             __float2bfloat16(v.y - __bfloat162float(h1)),
             __float2bfloat16(v.z - __bfloat162float(h2)),
             __float2bfloat16(v.w - __bfloat162float(h3)));
}
__device__ __forceinline__ unsigned long long cvt4h(float4 v) {
    union { __half2 h2[2]; unsigned long long u; } t;
    t.h2[0] = __floats2half2_rn(v.x, v.y);
    t.h2[1] = __floats2half2_rn(v.z, v.w);
    return t.u;
}
__device__ __forceinline__ void st8b(__nv_bfloat16* p, unsigned long long v) {
    *(unsigned long long*)p = v;
}
__device__ __forceinline__ void st8h(__half* p, unsigned long long v) {
    *(unsigned long long*)p = v;
}
template <int N>
__device__ __forceinline__ void grid_barrier(int* ctr) {
    __threadfence();
    __syncthreads();
    if (threadIdx.x == 0) {
        atomicAdd(ctr, 1);
        volatile int* v = ctr;
        while (*v < N) { }
    }
    __syncthreads();
}
template <int N>
__device__ __forceinline__ void signal_wait(int* ctr) {
    __threadfence();
    __syncthreads();
    if (threadIdx.x == 0) {
        atomicAdd(ctr, 1);
        volatile int* v = ctr;
        while (*v < N) { }
    }
    __syncthreads();
}
__device__ __forceinline__ void wait_count(int* ctr, int target) {
    if (threadIdx.x == 0) {
        volatile int* v = ctr;
        while (*v < target) { }
    }
    __syncthreads();
}

// ---------------- one-time prep ----------------
#define N_EMB4 (Tt * Bb * Ee / 4)
#define GAG_Z  (NCH_G * 8192 * 2 / 16)
#define N_CTR  (1 + 3 * Tt + Tt + Tt)
__global__ void prep_misc_kernel(const float* __restrict__ b_ih, const float* __restrict__ b_hh,
                                 const float* __restrict__ qz_b, const float* __restrict__ prior_b,
                                 const float* __restrict__ embed_W, const int* __restrict__ captions) {
    int i4 = blockIdx.x * blockDim.x + threadIdx.x;
    if (i4 < N_EMB4) {
        int j = i4 * 4;
        int tb = j >> 9, e = j & 511;
        int t = tb / Bb, b = tb % Bb;
        *(float4*)(g_emb + j) = *(const float4*)(embed_W + (size_t)captions[b * Tt + t] * Ee + e);
        return;
    }
    i4 -= N_EMB4;
    if (i4 < 512) {
        int n = i4 * 4;
        float4 a = *(const float4*)(b_ih + n), b = *(const float4*)(b_hh + n);
        *(float4*)(g_bsum + n) = make_float4(a.x + b.x, a.y + b.y, a.z + b.z, a.w + b.w);
        return;
    }
    i4 -= 512;
    if (i4 < 256) {
        int n = i4 * 4;
        *(float4*)(g_bias_pq + n) = (n < 512) ? *(const float4*)(qz_b + n)
                                              : *(const float4*)(prior_b + n - 512);
        return;
    }
    i4 -= 256;
    if (i4 < Bb * Hh / 4) { *(float4*)(g_c + i4 * 4) = make_float4(0, 0, 0, 0); return; }
    i4 -= Bb * Hh / 4;
    if (i4 < GAG_Z) { *(float4*)((char*)gAg + (size_t)i4 * 16) = make_float4(0, 0, 0, 0); return; }
    i4 -= GAG_Z;
    if (i4 < N_CTR) {
        if (i4 == 0) g_ctrP = 0;
        else if (i4 < 1 + 3 * Tt) { int j = i4 - 1; g_bar3[j / 3][j % 3] = 0; }
        else if (i4 < 1 + 3 * Tt + Tt) g_flagZ[i4 - 1 - 3 * Tt] = 0;
        else g_flagQ[i4 - 1 - 4 * Tt] = 0;
    }
}
#define PREP_MISC_TOT (N_EMB4 + 512 + 256 + Bb * Hh / 4 + GAG_Z + N_CTR)

// gates weights: N=2048, K order [e(512), z(256), h(512)], fold [hi|lo|hi]
__global__ void prep_wg_kernel(const float* __restrict__ W_ih, const float* __restrict__ W_hh) {
    int idx = blockIdx.x * blockDim.x + threadIdx.x;
    if (idx >= 2048 * 320) return;
    int n = idx / 320, k = (idx - n * 320) * 4;
    float4 v = (k < 768) ? *(const float4*)(W_ih + (size_t)n * 768 + k)
                         : *(const float4*)(W_hh + (size_t)n * 512 + (k - 768));
    unsigned long long hi, lo;
    cvt4(v, hi, lo);
    int tile = n >> 7, row = n & 127;
    __nv_bfloat16* base = gBg + (size_t)tile * NCH_G * 8192;
    st8b(base + ipos(k, row), hi);
    st8b(base + ipos(k + 1280, row), lo);
    st8b(base + ipos(k + 2560, row), hi);
}

// pq weights: N=1024 (qz 0-511, prior 512-1023 padded over e), K order [e, h]
__global__ void prep_wpq_kernel(const float* __restrict__ qz_W, const float* __restrict__ prior_W) {
    int idx = blockIdx.x * blockDim.x + threadIdx.x;
    if (idx >= 1024 * 256) return;
    int n = idx >> 8, k = (idx & 255) << 2;
    float4 v;
    if (n < 512) v = *(const float4*)(qz_W + (size_t)n * 1024 + k);
    else if (k < 512) v = make_float4(0, 0, 0, 0);
    else v = *(const float4*)(prior_W + (size_t)(n - 512) * 512 + (k - 512));
    unsigned long long hi, lo;
    cvt4(v, hi, lo);
    int tile = n >> 7, row = n & 127;
    __nv_bfloat16* base = gBpq + (size_t)tile * NCH_PQ * 8192;
    st8b(base + ipos(k, row), hi);
    st8b(base + ipos(k + 1024, row), lo);
    st8b(base + ipos(k + 2048, row), hi);
}

// qx weights fp16 single: [tile 84][chunk 12][192 x 64]
__global__ void prep_wqx_kernel(const float* __restrict__ qx_W) {
    int idx = blockIdx.x * blockDim.x + threadIdx.x;
    if (idx >= 16128 * 192) return;
    int n = idx / 192, k = (idx - n * 192) * 4;
    float4 v = (n < Vv) ? *(const float4*)(qx_W + (size_t)n * 768 + k)
                        : make_float4(0, 0, 0, 0);
    int tile = n / QROWS, row = n - tile * QROWS;
    __half* base = gBqx + (size_t)tile * (QCH * QROWS * 64);
    st8h(base + (size_t)(k >> 6) * (QROWS * 64) + row * 64 + (k & 63), cvt4h(v));
}

// features A-image (initial step): e-section of gAg (z,h sections pre-zeroed)
__global__ void build_feat_kernel(const float* __restrict__ features) {
    int i4 = blockIdx.x * 512 + threadIdx.x;
    int m = i4 >> 7;
    int e = (i4 & 127) << 2;
    float4 v = *(const float4*)(features + (size_t)m * 512 + e);
    unsigned long long hi, lo;
    cvt4(v, hi, lo);
    st8b(gAg + ipos(e, m), hi);
    st8b(gAg + ipos(e + 1280, m), hi);
    st8b(gAg + ipos(e + 2560, m), lo);
}

// ---------------- folded bf16 GEMM body (pq/gates; 128x128 tiles, 3-stage) ----------------
#define PITCH 144
#define STAGE_B 18432
#define SSZ128 ((128 + 128) * PITCH)
#define SM128 (3 * SSZ128)

__device__ __forceinline__ void load_stage(uint32_t st, const char* srcA, const char* srcB, int tid) {
#pragma unroll
    for (int j = 0; j < 4; j++) {
        int i = tid + j * 256;
        cpasync16(st + (i >> 3) * PITCH + (i & 7) * 16, srcA + i * 16);
    }
#pragma unroll
    for (int j = 0; j < 4; j++) {
        int i = tid + j * 256;
        cpasync16(st + STAGE_B + (i >> 3) * PITCH + (i & 7) * 16, srcB + i * 16);
    }
    asm volatile("cp.async.commit_group;" ::: "memory");
}

__device__ __forceinline__ void gemm_body(
    const __nv_bfloat16* __restrict__ Aimg, const __nv_bfloat16* __restrict__ Bimg,
    int nchunk, float* __restrict__ dst, int ldc, int n0) {
    extern __shared__ __align__(16) char smem[];
    const uint32_t sb = s2u(smem);
    const int tid = threadIdx.x;
    const int wid = tid >> 5;
    const int lane = tid & 31;
    const int warp_m = wid >> 2;
    const int warp_n = wid & 3;

    const char* gA = (const char*)Aimg;
    const char* gB = (const char*)Bimg;

    float acc[4][4][4];
#pragma unroll
    for (int i = 0; i < 4; i++)
#pragma unroll
        for (int j = 0; j < 4; j++)
#pragma unroll
            for (int q = 0; q < 4; q++) acc[i][j][q] = 0.0f;

    const int a_row = lane & 15;
    const int a_coff = (lane >> 4) << 4;
    const int b_row = ((lane >> 4) << 3) | (lane & 7);
    const int b_coff = ((lane >> 3) & 1) << 4;

#pragma unroll
    for (int s = 0; s < 3; s++)
        load_stage(sb + s * SSZ128, gA + (size_t)s * 16384, gB + (size_t)s * 16384, tid);

    int slot = 0;
    for (int c = 0; c < nchunk; c++) {
        asm volatile("cp.async.wait_group 2;" ::: "memory");
        __syncthreads();

        const uint32_t As = sb + slot * SSZ128;
        const uint32_t Bs = As + STAGE_B;
#pragma unroll
        for (int ks = 0; ks < 4; ks++) {
            uint32_t a[4][4];
#pragma unroll
            for (int mi = 0; mi < 4; mi++)
                ldmatrix_x4(a[mi], As + (uint32_t)(warp_m * 64 + mi * 16 + a_row) * PITCH +
                                    ks * 32 + a_coff);
#pragma unroll
            for (int jp = 0; jp < 2; jp++) {
                uint32_t b[4];
                ldmatrix_x4(b, Bs + (uint32_t)(warp_n * 32 + jp * 16 + b_row) * PITCH +
                                ks * 32 + b_coff);
#pragma unroll
                for (int mi = 0; mi < 4; mi++) {
                    mma_bf16(acc[mi][jp * 2 + 0], a[mi], b[0], b[1]);
                    mma_bf16(acc[mi][jp * 2 + 1], a[mi], b[2], b[3]);
                }
            }
        }
        __syncthreads();
        if (c + 3 < nchunk)
            load_stage(sb + slot * SSZ128, gA + (size_t)(c + 3) * 16384,
                       gB + (size_t)(c + 3) * 16384, tid);
        else
            asm volatile("cp.async.commit_group;" ::: "memory");
        slot = (slot == 2) ? 0 : slot + 1;
    }

    const int g = lane >> 2, tq = lane & 3;
#pragma unroll
    for (int mi = 0; mi < 4; mi++) {
        int row = warp_m * 64 + mi * 16 + g;
#pragma unroll
        for (int nj = 0; nj < 4; nj++) {
            int col = n0 + warp_n * 32 + nj * 8 + 2 * tq;
            *(float2*)(dst + (size_t)row * ldc + col) = make_float2(acc[mi][nj][0], acc[mi][nj][1]);
            *(float2*)(dst + (size_t)(row + 8) * ldc + col) = make_float2(acc[mi][nj][2], acc[mi][nj][3]);
        }
    }
}

// ---------------- recurrence tails ----------------
__device__ __forceinline__ void z_tail_body(const float* __restrict__ noise,
                                            float* __restrict__ out, int t) {
    __half* aqx = gAqx3[t % 3];
    for (int i4 = blockIdx.x * 256 + threadIdx.x; i4 < Bb * Ll / 4; i4 += REC_CTAS * 256) {
        int m = i4 >> 6;
        int l = (i4 & 63) << 2;
        const int r = m * 1024;
#define SUM8(off) ({ \
        float4 s = *(const float4*)(g_bias_pq + (off)); \
        _Pragma("unroll") \
        for (int sg = 0; sg < 8; sg++) { \
            float4 a = __ldcg((const float4*)(&g_pqp[sg][0] + r + (off))); \
            s.x += a.x; s.y += a.y; s.z += a.z; s.w += a.w; \
        } s; })
        float4 qmu = SUM8(l);
        float4 qsig = SUM8(256 + l);
        float4 pmu = SUM8(512 + l);
        float4 psig = SUM8(768 + l);
#undef SUM8
        size_t o = ((size_t)t * Bb + m) * Ll + l;
        *(float4*)(out + OFF_QMU + o) = qmu;
        *(float4*)(out + OFF_QSIG + o) = qsig;
        *(float4*)(out + OFF_PMU + o) = pmu;
        *(float4*)(out + OFF_PSIG + o) = psig;
        float4 nz = *(const float4*)(noise + ((size_t)m * Tt + t) * Ll + l);
        float4 z = make_float4(nz.x * qsig.x + qmu.x, nz.y * qsig.y + qmu.y,
                               nz.z * qsig.z + qmu.z, nz.w * qsig.w + qmu.w);
        unsigned long long hi, lo;
        cvt4(z, hi, lo);
        int kg = 512 + l;
        st8b(gAg + ipos(kg, m), hi);
        st8b(gAg + ipos(kg + 1280, m), hi);
        st8b(gAg + ipos(kg + 2560, m), lo);
        st8h(aqx + qpos16(l, m), cvt4h(z));
    }
}

__device__ __forceinline__ void lstm_tail_body(int t_next) {
    __half* aqx = gAqx3[t_next % 3];
    for (int i4 = blockIdx.x * 256 + threadIdx.x; i4 < Bb * Hh / 4; i4 += REC_CTAS * 256) {
        int b = i4 >> 7;
        int n = (i4 & 127) << 2;
        const int r = b * 2048;
#define GSUM(off) ({ \
        float4 s = *(const float4*)(g_bsum + (off)); \
        _Pragma("unroll") \
        for (int sg = 0; sg < 4; sg++) { \
            float4 a = __ldcg((const float4*)(&g_gp[sg][0] + r + (off))); \
            s.x += a.x; s.y += a.y; s.z += a.z; s.w += a.w; \
        } s; })
        float4 gi = GSUM(n);
        float4 gf = GSUM(512 + n);
        float4 gg = GSUM(1024 + n);
        float4 go = GSUM(1536 + n);
#undef GSUM
        float4 co = *(const float4*)(g_c + b * 512 + n);
        float4 cn, h;
        cn.x = sigf(gf.x) * co.x + sigf(gi.x) * tanhf(gg.x);
        cn.y = sigf(gf.y) * co.y + sigf(gi.y) * tanhf(gg.y);
        cn.z = sigf(gf.z) * co.z + sigf(gi.z) * tanhf(gg.z);
        cn.w = sigf(gf.w) * co.w + sigf(gi.w) * tanhf(gg.w);
        h.x = sigf(go.x) * tanhf(cn.x);
        h.y = sigf(go.y) * tanhf(cn.y);
        h.z = sigf(go.z) * tanhf(cn.z);
        h.w = sigf(go.w) * tanhf(cn.w);
        *(float4*)(g_c + b * 512 + n) = cn;
        unsigned long long hi, lo;
        cvt4(h, hi, lo);
        int k = 512 + n;
        st8b(gApq + ipos(k, b), hi);
        st8b(gApq + ipos(k + 1024, b), hi);
        st8b(gApq + ipos(k + 2048, b), lo);
        int kg = 768 + n;
        st8b(gAg + ipos(kg, b), hi);
        st8b(gAg + ipos(kg + 1280, b), hi);
        st8b(gAg + ipos(kg + 2560, b), lo);
        st8h(aqx + qpos16(256 + n, b), cvt4h(h));
    }
    if (t_next < Tt) {
        const float* src = g_emb + (((size_t)t_next * Bb) << 9);
        for (int i4 = blockIdx.x * 256 + threadIdx.x; i4 < Bb * Ee / 4; i4 += REC_CTAS * 256) {
            int m = i4 >> 7;
            int e = (i4 & 127) << 2;
            float4 v = *(const float4*)(src + ((size_t)m << 9) + e);
            unsigned long long hi, lo;
            cvt4(v, hi, lo);
            st8b(gApq + ipos(e, m), hi);
            st8b(gApq + ipos(e + 1024, m), hi);
            st8b(gApq + ipos(e + 2048, m), lo);
            st8b(gAg + ipos(e, m), hi);
            st8b(gAg + ipos(e + 1280, m), hi);
            st8b(gAg + ipos(e + 2560, m), lo);
        }
    }
}

// ---------------- prologue: gates GEMM + LSTM tail (t=0 images) ----------------
__global__ void __launch_bounds__(256) prolog_kernel() {
    int seg = blockIdx.x >> 4, tile = blockIdx.x & 15;
    gemm_body(gAg + (size_t)seg * 15 * 8192,
              gBg + ((size_t)tile * NCH_G + seg * 15) * 8192,
              15, g_gp[seg], 2048, tile << 7);
    grid_barrier<REC_CTAS>(&g_ctrP);
    lstm_tail_body(0);
}

// ---------------- fused 2-step recurrence kernel (64 CTAs) ----------------
__global__ void __launch_bounds__(256) rec_step2_kernel(const float* __restrict__ noise,
                                                        float* __restrict__ out, int t0) {
    for (int t = t0; t < t0 + 2; t++) {
        {
            int seg = blockIdx.x >> 3, tile = blockIdx.x & 7;
            gemm_body(gApq + (size_t)seg * 6 * 8192,
                      gBpq + ((size_t)tile * NCH_PQ + seg * 6) * 8192,
                      6, g_pqp[seg], 1024, tile << 7);
        }
        grid_barrier<REC_CTAS>(&g_bar3[t][0]);
        z_tail_body(noise, out, t);
        signal_wait<REC_CTAS>(&g_flagZ[t]);   // barrier + producer signal for qx_persist
        {
            int seg = blockIdx.x >> 4, tile = blockIdx.x & 15;
            gemm_body(gAg + (size_t)seg * 15 * 8192,
                      gBg + ((size_t)tile * NCH_G + seg * 15) * 8192,
                      15, g_gp[seg], 2048, tile << 7);
        }
        grid_barrier<REC_CTAS>(&g_bar3[t][1]);
        // lstm_tail(t+1) writes qx A-buffer (t+1)%3, last read by qx(t-2)
        if (t >= 2) wait_count(&g_flagQ[t - 2], QX_CTAS);
        lstm_tail_body(t + 1);
        // all images complete before next iteration's pq GEMM reads them
        grid_barrier<REC_CTAS>(&g_bar3[t][2]);
    }
}

// ---------------- persistent qx GEMM + fused softmax (84 CTAs, fp16, 3-stage) ----------------
#define STAGE_A16 (128 * PITCH)             // 18432
#define QSTG ((128 + 192) * PITCH)          // 46080
#define SMQX (3 * QSTG)                     // 138240

__device__ __forceinline__ void load_stage_qx(uint32_t st, const char* srcA, const char* srcB,
                                              int tid) {
#pragma unroll
    for (int j = 0; j < 4; j++) {
        int i = tid + j * 256;
        cpasync16(st + (i >> 3) * PITCH + (i & 7) * 16, srcA + i * 16);
    }
#pragma unroll
    for (int j = 0; j < 6; j++) {
        int i = tid + j * 256;
        cpasync16(st + STAGE_A16 + (i >> 3) * PITCH + (i & 7) * 16, srcB + i * 16);
    }
    asm volatile("cp.async.commit_group;" ::: "memory");
}

// combine partials for one row and subtract lz (block-wide)
__device__ void combine_subtract(float* __restrict__ x, const float* __restrict__ smaxr,
                                 const float* __restrict__ ssumr) {
    __shared__ float cred[8];
    __shared__ float cval;
    const int tid = threadIdx.x;
    float m = -3.4e38f;
    for (int i = tid; i < QX_CTAS; i += 256) m = fmaxf(m, __ldcg(smaxr + i));
#pragma unroll
    for (int o = 16; o; o >>= 1) m = fmaxf(m, __shfl_xor_sync(0xffffffffu, m, o));
    if ((tid & 31) == 0) cred[tid >> 5] = m;
    __syncthreads();
    if (tid < 32) {
        float v = (tid < 8) ? cred[tid] : -3.4e38f;
#pragma unroll
        for (int o = 4; o; o >>= 1) v = fmaxf(v, __shfl_xor_sync(0xffffffffu, v, o));
        if (tid == 0) cval = v;
    }
    __syncthreads();
    float gmax = cval;
    float s = 0.0f;
    for (int i = tid; i < QX_CTAS; i += 256)
        s += __ldcg(ssumr + i) * expf(__ldcg(smaxr + i) - gmax);
#pragma unroll
    for (int o = 16; o; o >>= 1) s += __shfl_xor_sync(0xffffffffu, s, o);
    __syncthreads();
    if ((tid & 31) == 0) cred[tid >> 5] = s;
    __syncthreads();
    if (tid < 32) {
        float v = (tid < 8) ? cred[tid] : 0.0f;
#pragma unroll
        for (int o = 4; o; o >>= 1) v += __shfl_xor_sync(0xffffffffu, v, o);
        if (tid == 0) cval = gmax + logf(v);
    }
    __syncthreads();
    float lz = cval;
    for (int i = tid; i < Vv; i += 256) x[i] -= lz;
    __syncthreads();
}

__global__ void __launch_bounds__(256) qx_persist_kernel(const float* __restrict__ qx_b,
                                                         float* __restrict__ out) {
    extern __shared__ __align__(16) char smem[];
    const uint32_t sb = s2u(smem);
    float* red = (float*)smem;             // reused after GEMM: [0..511] max, [512..1023] sum
    const int tid = threadIdx.x;
    const int wid = tid >> 5;
    const int lane = tid & 31;
    const int warp_m = wid >> 2;
    const int warp_n = wid & 3;
    const int n0 = blockIdx.x * QROWS;

    const char* gB = (const char*)(gBqx + (size_t)blockIdx.x * (QCH * QROWS * 64));

    const int a_row = lane & 15;
    const int a_coff = (lane >> 4) << 4;
    const int b_row = ((lane >> 4) << 3) | (lane & 7);
    const int b_coff = ((lane >> 3) & 1) << 4;
    const int g = lane >> 2, tq = lane & 3;

    for (int t = 0; t < Tt; t++) {
        wait_count(&g_flagZ[t], REC_CTAS);

        float* dst = out + OFF_QX + (size_t)t * Bb * Vv;
        const char* gA = (const char*)gAqx3[t % 3];
        const int buf = t & 1;

        float acc[4][6][4];
#pragma unroll
        for (int i = 0; i < 4; i++)
#pragma unroll
            for (int j = 0; j < 6; j++)
#pragma unroll
                for (int q = 0; q < 4; q++) acc[i][j][q] = 0.0f;

#pragma unroll
        for (int s = 0; s < 3; s++)
            load_stage_qx(sb + s * QSTG, gA + (size_t)s * 16384, gB + (size_t)s * 24576, tid);

        int slot = 0;
        for (int c = 0; c < QCH; c++) {
            asm volatile("cp.async.wait_group 2;" ::: "memory");
            __syncthreads();

            const uint32_t As = sb + slot * QSTG;
            const uint32_t Bs = As + STAGE_A16;
#pragma unroll
            for (int ks = 0; ks < 4; ks++) {
                uint32_t a[4][4];
#pragma unroll
                for (int mi = 0; mi < 4; mi++)
                    ldmatrix_x4(a[mi], As + (uint32_t)(warp_m * 64 + mi * 16 + a_row) * PITCH +
                                        ks * 32 + a_coff);
#pragma unroll
                for (int jp = 0; jp < 3; jp++) {
                    uint32_t b[4];
                    ldmatrix_x4(b, Bs + (uint32_t)(warp_n * 48 + jp * 16 + b_row) * PITCH +
                                    ks * 32 + b_coff);
#pragma unroll
                    for (int mi = 0; mi < 4; mi++) {
                        mma_f16(acc[mi][jp * 2 + 0], a[mi], b[0], b[1]);
                        mma_f16(acc[mi][jp * 2 + 1], a[mi], b[2], b[3]);
                    }
                }
            }
            __syncthreads();
            if (c + 3 < QCH)
                load_stage_qx(sb + slot * QSTG, gA + (size_t)(c + 3) * 16384,
                              gB + (size_t)(c + 3) * 24576, tid);
            else
                asm volatile("cp.async.commit_group;" ::: "memory");
            slot = (slot == 2) ? 0 : slot + 1;
        }
        __syncthreads();   // GEMM smem no longer needed; red[] reuse is safe

        // epilogue: write logits + per-thread partial max
        float pmax[4][2];
#pragma unroll
        for (int mi = 0; mi < 4; mi++) { pmax[mi][0] = -3.4e38f; pmax[mi][1] = -3.4e38f; }
#pragma unroll
        for (int mi = 0; mi < 4; mi++) {
            int row = warp_m * 64 + mi * 16 + g;
#pragma unroll
            for (int nj = 0; nj < 6; nj++) {
                int col = n0 + warp_n * 48 + nj * 8 + 2 * tq;
                if (col >= Vv) continue;
                float b0 = qx_b[col], b1 = qx_b[col + 1];
                float v00 = acc[mi][nj][0] + b0, v01 = acc[mi][nj][1] + b1;
                float v10 = acc[mi][nj][2] + b0, v11 = acc[mi][nj][3] + b1;
                *(float2*)(dst + (size_t)row * Vv + col) = make_float2(v00, v01);
                *(float2*)(dst + (size_t)(row + 8) * Vv + col) = make_float2(v10, v11);
                pmax[mi][0] = fmaxf(pmax[mi][0], fmaxf(v00, v01));
                pmax[mi][1] = fmaxf(pmax[mi][1], fmaxf(v10, v11));
            }
        }
        // reduce max over tq (lanes differ only in bits 0-1 within same g-group)
#pragma unroll
        for (int mi = 0; mi < 4; mi++)
#pragma unroll
            for (int h = 0; h < 2; h++) {
                float v = pmax[mi][h];
                v = fmaxf(v, __shfl_xor_sync(0xffffffffu, v, 1));
                v = fmaxf(v, __shfl_xor_sync(0xffffffffu, v, 2));
                pmax[mi][h] = v;
            }
        if (tq == 0) {
#pragma unroll
            for (int mi = 0; mi < 4; mi++)
#pragma unroll
                for (int h = 0; h < 2; h++)
                    red[warp_n * 128 + (warp_m * 64 + mi * 16 + h * 8 + g)] = pmax[mi][h];
        }
        __syncthreads();
        float tmax[4][2];
#pragma unroll
        for (int mi = 0; mi < 4; mi++)
#pragma unroll
            for (int h = 0; h < 2; h++) {
                int row = warp_m * 64 + mi * 16 + h * 8 + g;
                float v = red[row];
#pragma unroll
                for (int w = 1; w < 4; w++) v = fmaxf(v, red[w * 128 + row]);
                tmax[mi][h] = v;
            }
        // per-thread partial sumexp
        float psum[4][2];
#pragma unroll
        for (int mi = 0; mi < 4; mi++) { psum[mi][0] = 0.0f; psum[mi][1] = 0.0f; }
#pragma unroll
        for (int mi = 0; mi < 4; mi++) {
#pragma unroll
            for (int nj = 0; nj < 6; nj++) {
                int col = n0 + warp_n * 48 + nj * 8 + 2 * tq;
                if (col >= Vv) continue;
                float b0 = qx_b[col], b1 = qx_b[col + 1];
                psum[mi][0] += expf(acc[mi][nj][0] + b0 - tmax[mi][0]) +
                               expf(acc[mi][nj][1] + b1 - tmax[mi][0]);
                psum[mi][1] += expf(acc[mi][nj][2] + b0 - tmax[mi][1]) +
                               expf(acc[mi][nj][3] + b1 - tmax[mi][1]);
            }
        }
#pragma unroll
        for (int mi = 0; mi < 4; mi++)
#pragma unroll
            for (int h = 0; h < 2; h++) {
                float v = psum[mi][h];
                v += __shfl_xor_sync(0xffffffffu, v, 1);
                v += __shfl_xor_sync(0xffffffffu, v, 2);
                psum[mi][h] = v;
            }
        if (tq == 0) {
#pragma unroll
            for (int mi = 0; mi < 4; mi++)
#pragma unroll
                for (int h = 0; h < 2; h++)
                    red[512 + warp_n * 128 + (warp_m * 64 + mi * 16 + h * 8 + g)] = psum[mi][h];
        }
        __syncthreads();
        if (warp_n == 0 && tq == 0) {
#pragma unroll
            for (int mi = 0; mi < 4; mi++)
#pragma unroll
                for (int h = 0; h < 2; h++) {
                    int row = warp_m * 64 + mi * 16 + h * 8 + g;
                    float v = red[512 + row];
#pragma unroll
                    for (int w = 1; w < 4; w++) v += red[512 + w * 128 + row];
                    g_smax[buf][row][blockIdx.x] = tmax[mi][h];
                    g_ssum[buf][row][blockIdx.x] = v;
                }
        }

        // partials + logits visible, signal rec (A-buffer free) + all-84 barrier
        signal_wait<QX_CTAS>(&g_flagQ[t]);

        combine_subtract(dst + (size_t)blockIdx.x * Vv,
                         &g_smax[buf][blockIdx.x][0], &g_ssum[buf][blockIdx.x][0]);
        if (blockIdx.x + QX_CTAS < Bb)
            combine_subtract(dst + (size_t)(blockIdx.x + QX_CTAS) * Vv,
                             &g_smax[buf][blockIdx.x + QX_CTAS][0],
                             &g_ssum[buf][blockIdx.x + QX_CTAS][0]);
    }
}

extern "C" void kernel_launch(void* const* d_in, const int* in_sizes, int n_in,
                              void* d_out, int out_size) {
    const float* features = (const float*)d_in[0];
    const int* captions = (const int*)d_in[1];
    const float* noise   = (const float*)d_in[3];
    const float* embed_W = (const float*)d_in[4];
    const float* W_ih    = (const float*)d_in[5];
    const float* W_hh    = (const float*)d_in[6];
    const float* b_ih    = (const float*)d_in[7];
    const float* b_hh    = (const float*)d_in[8];
    const float* qz_W    = (const float*)d_in[9];
    const float* qz_b    = (const float*)d_in[10];
    const float* prior_W = (const float*)d_in[11];
    const float* prior_b = (const float*)d_in[12];
    const float* qx_W    = (const float*)d_in[13];
    const float* qx_b    = (const float*)d_in[14];
    float* out = (float*)d_out;

    static cudaStream_t s1 = nullptr, s2 = nullptr;
    static cudaEvent_t evF = nullptr, evW = nullptr, evJ1 = nullptr;
    if (s1 == nullptr) {
        cudaStreamCreateWithFlags(&s1, cudaStreamNonBlocking);
        cudaStreamCreateWithFlags(&s2, cudaStreamNonBlocking);
        cudaEventCreateWithFlags(&evF, cudaEventDisableTiming);
        cudaEventCreateWithFlags(&evW, cudaEventDisableTiming);
        cudaEventCreateWithFlags(&evJ1, cudaEventDisableTiming);
    }

    cudaFuncSetAttribute(prolog_kernel, cudaFuncAttributeMaxDynamicSharedMemorySize, SM128);
    cudaFuncSetAttribute(rec_step2_kernel, cudaFuncAttributeMaxDynamicSharedMemorySize, SM128);
    cudaFuncSetAttribute(qx_persist_kernel, cudaFuncAttributeMaxDynamicSharedMemorySize, SMQX);

    // one-time prep — fork side streams from the capture stream via an event
    prep_misc_kernel<<<(PREP_MISC_TOT + 255) / 256, 256>>>(b_ih, b_hh, qz_b, prior_b,
                                                           embed_W, captions);
    cudaEventRecord(evF, 0);
    cudaStreamWaitEvent(s1, evF, 0);
    cudaStreamWaitEvent(s2, evF, 0);
    prep_wqx_kernel<<<(16128 * 192 + 255) / 256, 256, 0, s1>>>(qx_W);
    prep_wg_kernel<<<(2048 * 320 + 255) / 256, 256, 0, s2>>>(W_ih, W_hh);
    prep_wpq_kernel<<<(1024 * 256 + 255) / 256, 256>>>(qz_W, prior_W);
    cudaEventRecord(evW, s2);
    cudaStreamWaitEvent(0, evW, 0);   // gBg ready before prolog on stream 0

    // persistent qx worker (spins on flagZ; launch on s1 after its weight prep)
    qx_persist_kernel<<<QX_CTAS, 256, SMQX, s1>>>(qx_b, out);

    // initial LSTM step: features through the gates tc path (z,h image sections are zero)
    build_feat_kernel<<<32, 512>>>(features);
    prolog_kernel<<<REC_CTAS, 256, SM128>>>();

    for (int t = 0; t < Tt; t += 2)
        rec_step2_kernel<<<REC_CTAS, 256, SM128>>>(noise, out, t);

    // join: wait for the persistent qx kernel
    cudaEventRecord(evJ1, s1);
    cudaStreamWaitEvent(0, evJ1, 0);
}

// round 16
// speedup vs baseline: 1.0475x; 1.0475x over previous
#include <cuda_runtime.h>
#include <cuda_bf16.h>
#include <cuda_fp16.h>
#include <math.h>
#include <stdint.h>

// Problem constants
#define Bb 128
#define Tt 32
#define Ee 512
#define Hh 512
#define Ll 256
#define Vv 16000

#define NCH_G  60      // gates: K2=3840 (folded bf16)
#define NCH_PQ 48      // pq: K2=3072 (folded bf16)
#define QROWS  192
#define QCH    12      // qx chunks of 64 over K=768 (fp16 single)
#define REC_CTAS 64
#define QX_CTAS  84

// Output layout: p_mus, p_sigmas, q_mus, q_sigmas, q_xs
#define OFF_PMU  ((size_t)0)
#define OFF_PSIG ((size_t)Tt * Bb * Ll)
#define OFF_QMU  ((size_t)2 * Tt * Bb * Ll)
#define OFF_QSIG ((size_t)3 * Tt * Bb * Ll)
#define OFF_QX   ((size_t)4 * Tt * Bb * Ll)

// ---------------- device scratch ----------------
__device__ float g_emb[Tt * Bb * Ee];
__device__ float g_bsum[4 * Hh];
__device__ float g_bias_pq[1024];
__device__ float g_c[Bb * Hh];
__device__ float g_pqp[8][Bb * 1024];
__device__ float g_gp[4][Bb * 2048];
__device__ int g_ctrP;
__device__ int g_bar2[Tt][2];            // rec_step internal barriers
__device__ int g_flagZ[Tt];              // z-images ready (==64)
__device__ int g_flagQ[Tt];              // qx GEMM done (==84)

// Weight images (once)
__device__ __align__(16) __nv_bfloat16 gBg[(size_t)16 * NCH_G * 8192];
__device__ __align__(16) __nv_bfloat16 gBpq[(size_t)8 * NCH_PQ * 8192];
__device__ __align__(16) __half gBqx[(size_t)QX_CTAS * QCH * QROWS * 64];   // fp16 single
// A images: pq/gates folded bf16 single; qx fp16 QUAD-buffered
__device__ __align__(16) __nv_bfloat16 gAg[NCH_G * 8192];
__device__ __align__(16) __nv_bfloat16 gApq[NCH_PQ * 8192];
__device__ __align__(16) __half gAqx4[4][QCH * 8192];

__device__ __forceinline__ float sigf(float x) { return 1.0f / (1.0f + expf(-x)); }

__device__ __forceinline__ uint32_t s2u(const void* p) {
    uint32_t a;
    asm("{ .reg .u64 t; cvta.to.shared.u64 t, %1; cvt.u32.u64 %0, t; }" : "=r"(a) : "l"(p));
    return a;
}
__device__ __forceinline__ void cpasync16(uint32_t dst, const void* src) {
    asm volatile("cp.async.cg.shared.global [%0], [%1], 16;"
                 :: "r"(dst), "l"(__cvta_generic_to_global(src)) : "memory");
}
__device__ __forceinline__ void ldmatrix_x4(uint32_t* r, uint32_t addr) {
    asm volatile("ldmatrix.sync.aligned.m8n8.x4.shared.b16 {%0,%1,%2,%3}, [%4];"
                 : "=r"(r[0]), "=r"(r[1]), "=r"(r[2]), "=r"(r[3]) : "r"(addr));
}
__device__ __forceinline__ void mma_bf16(float* c, const uint32_t* a, uint32_t b0, uint32_t b1) {
    asm volatile(
        "mma.sync.aligned.m16n8k16.row.col.f32.bf16.bf16.f32 "
        "{%0,%1,%2,%3}, {%4,%5,%6,%7}, {%8,%9}, {%0,%1,%2,%3};"
        : "+f"(c[0]), "+f"(c[1]), "+f"(c[2]), "+f"(c[3])
        : "r"(a[0]), "r"(a[1]), "r"(a[2]), "r"(a[3]), "r"(b0), "r"(b1));
}
__device__ __forceinline__ void mma_f16(float* c, const uint32_t* a, uint32_t b0, uint32_t b1) {
    asm volatile(
        "mma.sync.aligned.m16n8k16.row.col.f32.f16.f16.f32 "
        "{%0,%1,%2,%3}, {%4,%5,%6,%7}, {%8,%9}, {%0,%1,%2,%3};"
        : "+f"(c[0]), "+f"(c[1]), "+f"(c[2]), "+f"(c[3])
        : "r"(a[0]), "r"(a[1]), "r"(a[2]), "r"(a[3]), "r"(b0), "r"(b1));
}
__device__ __forceinline__ size_t ipos(int k2, int m) {      // bf16 folded images
    return (((size_t)(k2 >> 6) * 128 + m) << 6) + (k2 & 63);
}
__device__ __forceinline__ size_t qpos16(int k, int m) {     // fp16 qx A image
    return (size_t)(k >> 6) * 8192 + m * 64 + (k & 63);
}
__device__ __forceinline__ unsigned long long pk4(__nv_bfloat16 a, __nv_bfloat16 b,
                                                  __nv_bfloat16 c, __nv_bfloat16 d) {
    union { __nv_bfloat16 h[4]; unsigned long long u; } t;
    t.h[0] = a; t.h[1] = b; t.h[2] = c; t.h[3] = d;
    return t.u;
}
__device__ __forceinline__ void cvt4(float4 v, unsigned long long& hi, unsigned long long& lo) {
    __nv_bfloat16 h0 = __float2bfloat16(v.x), h1 = __float2bfloat16(v.y);
    __nv_bfloat16 h2 = __float2bfloat16(v.z), h3 = __float2bfloat16(v.w);
    hi = pk4(h0, h1, h2, h3);
    lo = pk4(__float2bfloat16(v.x - __bfloat162float(h0)),
             __float2bfloat16(v.y - __bfloat162float(h1)),
             __float2bfloat16(v.z - __bfloat162float(h2)),
             __float2bfloat16(v.w - __bfloat162float(h3)));
}
__device__ __forceinline__ unsigned long long cvt4h(float4 v) {
    union { __half2 h2[2]; unsigned long long u; } t;
    t.h2[0] = __floats2half2_rn(v.x, v.y);
    t.h2[1] = __floats2half2_rn(v.z, v.w);
    return t.u;
}
__device__ __forceinline__ void st8b(__nv_bfloat16* p, unsigned long long v) {
    *(unsigned long long*)p = v;
}
__device__ __forceinline__ void st8h(__half* p, unsigned long long v) {
    *(unsigned long long*)p = v;
}
template <int N>
__device__ __forceinline__ void grid_barrier(int* ctr) {
    __threadfence();
    __syncthreads();
    if (threadIdx.x == 0) {
        atomicAdd(ctr, 1);
        volatile int* v = ctr;
        while (*v < N) { }
    }
    __syncthreads();
}
template <int N>
__device__ __forceinline__ void signal_wait(int* ctr) {
    __threadfence();
    __syncthreads();
    if (threadIdx.x == 0) {
        atomicAdd(ctr, 1);
        volatile int* v = ctr;
        while (*v < N) { }
    }
    __syncthreads();
}
__device__ __forceinline__ void wait_count(int* ctr, int target) {
    if (threadIdx.x == 0) {
        volatile int* v = ctr;
        while (*v < target) { }
    }
    __syncthreads();
}

// ---------------- one-time prep ----------------
#define N_EMB4 (Tt * Bb * Ee / 4)
#define GAG_Z  (NCH_G * 8192 * 2 / 16)
#define N_CTR  (1 + 2 * Tt + Tt + Tt)
__global__ void prep_misc_kernel(const float* __restrict__ b_ih, const float* __restrict__ b_hh,
                                 const float* __restrict__ qz_b, const float* __restrict__ prior_b,
                                 const float* __restrict__ embed_W, const int* __restrict__ captions) {
    int i4 = blockIdx.x * blockDim.x + threadIdx.x;
    if (i4 < N_EMB4) {
        int j = i4 * 4;
        int tb = j >> 9, e = j & 511;
        int t = tb / Bb, b = tb % Bb;
        *(float4*)(g_emb + j) = *(const float4*)(embed_W + (size_t)captions[b * Tt + t] * Ee + e);
        return;
    }
    i4 -= N_EMB4;
    if (i4 < 512) {
        int n = i4 * 4;
        float4 a = *(const float4*)(b_ih + n), b = *(const float4*)(b_hh + n);
        *(float4*)(g_bsum + n) = make_float4(a.x + b.x, a.y + b.y, a.z + b.z, a.w + b.w);
        return;
    }
    i4 -= 512;
    if (i4 < 256) {
        int n = i4 * 4;
        *(float4*)(g_bias_pq + n) = (n < 512) ? *(const float4*)(qz_b + n)
                                              : *(const float4*)(prior_b + n - 512);
        return;
    }
    i4 -= 256;
    if (i4 < Bb * Hh / 4) { *(float4*)(g_c + i4 * 4) = make_float4(0, 0, 0, 0); return; }
    i4 -= Bb * Hh / 4;
    if (i4 < GAG_Z) { *(float4*)((char*)gAg + (size_t)i4 * 16) = make_float4(0, 0, 0, 0); return; }
    i4 -= GAG_Z;
    if (i4 < N_CTR) {
        if (i4 == 0) g_ctrP = 0;
        else if (i4 < 1 + 2 * Tt) { int j = i4 - 1; g_bar2[j >> 1][j & 1] = 0; }
        else if (i4 < 1 + 2 * Tt + Tt) g_flagZ[i4 - 1 - 2 * Tt] = 0;
        else g_flagQ[i4 - 1 - 3 * Tt] = 0;
    }
}
#define PREP_MISC_TOT (N_EMB4 + 512 + 256 + Bb * Hh / 4 + GAG_Z + N_CTR)

// gates weights: N=2048, K order [e(512), z(256), h(512)], fold [hi|lo|hi]
__global__ void prep_wg_kernel(const float* __restrict__ W_ih, const float* __restrict__ W_hh) {
    int idx = blockIdx.x * blockDim.x + threadIdx.x;
    if (idx >= 2048 * 320) return;
    int n = idx / 320, k = (idx - n * 320) * 4;
    float4 v = (k < 768) ? *(const float4*)(W_ih + (size_t)n * 768 + k)
                         : *(const float4*)(W_hh + (size_t)n * 512 + (k - 768));
    unsigned long long hi, lo;
    cvt4(v, hi, lo);
    int tile = n >> 7, row = n & 127;
    __nv_bfloat16* base = gBg + (size_t)tile * NCH_G * 8192;
    st8b(base + ipos(k, row), hi);
    st8b(base + ipos(k + 1280, row), lo);
    st8b(base + ipos(k + 2560, row), hi);
}

// pq weights: N=1024 (qz 0-511, prior 512-1023 padded over e), K order [e, h]
__global__ void prep_wpq_kernel(const float* __restrict__ qz_W, const float* __restrict__ prior_W) {
    int idx = blockIdx.x * blockDim.x + threadIdx.x;
    if (idx >= 1024 * 256) return;
    int n = idx >> 8, k = (idx & 255) << 2;
    float4 v;
    if (n < 512) v = *(const float4*)(qz_W + (size_t)n * 1024 + k);
    else if (k < 512) v = make_float4(0, 0, 0, 0);
    else v = *(const float4*)(prior_W + (size_t)(n - 512) * 512 + (k - 512));
    unsigned long long hi, lo;
    cvt4(v, hi, lo);
    int tile = n >> 7, row = n & 127;
    __nv_bfloat16* base = gBpq + (size_t)tile * NCH_PQ * 8192;
    st8b(base + ipos(k, row), hi);
    st8b(base + ipos(k + 1024, row), lo);
    st8b(base + ipos(k + 2048, row), hi);
}

// qx weights fp16 single: [tile 84][chunk 12][192 x 64]
__global__ void prep_wqx_kernel(const float* __restrict__ qx_W) {
    int idx = blockIdx.x * blockDim.x + threadIdx.x;
    if (idx >= 16128 * 192) return;
    int n = idx / 192, k = (idx - n * 192) * 4;
    float4 v = (n < Vv) ? *(const float4*)(qx_W + (size_t)n * 768 + k)
                        : make_float4(0, 0, 0, 0);
    int tile = n / QROWS, row = n - tile * QROWS;
    __half* base = gBqx + (size_t)tile * (QCH * QROWS * 64);
    st8h(base + (size_t)(k >> 6) * (QROWS * 64) + row * 64 + (k & 63), cvt4h(v));
}

// features A-image (initial step): e-section of gAg (z,h sections pre-zeroed)
__global__ void build_feat_kernel(const float* __restrict__ features) {
    int i4 = blockIdx.x * 512 + threadIdx.x;
    int m = i4 >> 7;
    int e = (i4 & 127) << 2;
    float4 v = *(const float4*)(features + (size_t)m * 512 + e);
    unsigned long long hi, lo;
    cvt4(v, hi, lo);
    st8b(gAg + ipos(e, m), hi);
    st8b(gAg + ipos(e + 1280, m), hi);
    st8b(gAg + ipos(e + 2560, m), lo);
}

// ---------------- folded bf16 GEMM body (pq/gates; 128x128 tiles, 3-stage) ----------------
#define PITCH 144
#define STAGE_B 18432
#define SSZ128 ((128 + 128) * PITCH)
#define SM128 (3 * SSZ128)

__device__ __forceinline__ void load_stage(uint32_t st, const char* srcA, const char* srcB, int tid) {
#pragma unroll
    for (int j = 0; j < 4; j++) {
        int i = tid + j * 256;
        cpasync16(st + (i >> 3) * PITCH + (i & 7) * 16, srcA + i * 16);
    }
#pragma unroll
    for (int j = 0; j < 4; j++) {
        int i = tid + j * 256;
        cpasync16(st + STAGE_B + (i >> 3) * PITCH + (i & 7) * 16, srcB + i * 16);
    }
    asm volatile("cp.async.commit_group;" ::: "memory");
}

__device__ __forceinline__ void gemm_body(
    const __nv_bfloat16* __restrict__ Aimg, const __nv_bfloat16* __restrict__ Bimg,
    int nchunk, float* __restrict__ dst, int ldc, int n0) {
    extern __shared__ __align__(16) char smem[];
    const uint32_t sb = s2u(smem);
    const int tid = threadIdx.x;
    const int wid = tid >> 5;
    const int lane = tid & 31;
    const int warp_m = wid >> 2;
    const int warp_n = wid & 3;

    const char* gA = (const char*)Aimg;
    const char* gB = (const char*)Bimg;

    float acc[4][4][4];
#pragma unroll
    for (int i = 0; i < 4; i++)
#pragma unroll
        for (int j = 0; j < 4; j++)
#pragma unroll
            for (int q = 0; q < 4; q++) acc[i][j][q] = 0.0f;

    const int a_row = lane & 15;
    const int a_coff = (lane >> 4) << 4;
    const int b_row = ((lane >> 4) << 3) | (lane & 7);
    const int b_coff = ((lane >> 3) & 1) << 4;

#pragma unroll
    for (int s = 0; s < 3; s++)
        load_stage(sb + s * SSZ128, gA + (size_t)s * 16384, gB + (size_t)s * 16384, tid);

    int slot = 0;
    for (int c = 0; c < nchunk; c++) {
        asm volatile("cp.async.wait_group 2;" ::: "memory");
        __syncthreads();

        const uint32_t As = sb + slot * SSZ128;
        const uint32_t Bs = As + STAGE_B;
#pragma unroll
        for (int ks = 0; ks < 4; ks++) {
            uint32_t a[4][4];
#pragma unroll
            for (int mi = 0; mi < 4; mi++)
                ldmatrix_x4(a[mi], As + (uint32_t)(warp_m * 64 + mi * 16 + a_row) * PITCH +
                                    ks * 32 + a_coff);
#pragma unroll
            for (int jp = 0; jp < 2; jp++) {
                uint32_t b[4];
                ldmatrix_x4(b, Bs + (uint32_t)(warp_n * 32 + jp * 16 + b_row) * PITCH +
                                ks * 32 + b_coff);
#pragma unroll
                for (int mi = 0; mi < 4; mi++) {
                    mma_bf16(acc[mi][jp * 2 + 0], a[mi], b[0], b[1]);
                    mma_bf16(acc[mi][jp * 2 + 1], a[mi], b[2], b[3]);
                }
            }
        }
        __syncthreads();
        if (c + 3 < nchunk)
            load_stage(sb + slot * SSZ128, gA + (size_t)(c + 3) * 16384,
                       gB + (size_t)(c + 3) * 16384, tid);
        else
            asm volatile("cp.async.commit_group;" ::: "memory");
        slot = (slot == 2) ? 0 : slot + 1;
    }

    const int g = lane >> 2, tq = lane & 3;
#pragma unroll
    for (int mi = 0; mi < 4; mi++) {
        int row = warp_m * 64 + mi * 16 + g;
#pragma unroll
        for (int nj = 0; nj < 4; nj++) {
            int col = n0 + warp_n * 32 + nj * 8 + 2 * tq;
            *(float2*)(dst + (size_t)row * ldc + col) = make_float2(acc[mi][nj][0], acc[mi][nj][1]);
            *(float2*)(dst + (size_t)(row + 8) * ldc + col) = make_float2(acc[mi][nj][2], acc[mi][nj][3]);
        }
    }
}

// ---------------- recurrence tails ----------------
__device__ __forceinline__ void z_tail_body(const float* __restrict__ noise,
                                            float* __restrict__ out, int t) {
    __half* aqx = gAqx4[t & 3];
    for (int i4 = blockIdx.x * 256 + threadIdx.x; i4 < Bb * Ll / 4; i4 += REC_CTAS * 256) {
        int m = i4 >> 6;
        int l = (i4 & 63) << 2;
        const int r = m * 1024;
#define SUM8(off) ({ \
        float4 s = *(const float4*)(g_bias_pq + (off)); \
        _Pragma("unroll") \
        for (int sg = 0; sg < 8; sg++) { \
            float4 a = __ldcg((const float4*)(&g_pqp[sg][0] + r + (off))); \
            s.x += a.x; s.y += a.y; s.z += a.z; s.w += a.w; \
        } s; })
        float4 qmu = SUM8(l);
        float4 qsig = SUM8(256 + l);
        float4 pmu = SUM8(512 + l);
        float4 psig = SUM8(768 + l);
#undef SUM8
        size_t o = ((size_t)t * Bb + m) * Ll + l;
        *(float4*)(out + OFF_QMU + o) = qmu;
        *(float4*)(out + OFF_QSIG + o) = qsig;
        *(float4*)(out + OFF_PMU + o) = pmu;
        *(float4*)(out + OFF_PSIG + o) = psig;
        float4 nz = *(const float4*)(noise + ((size_t)m * Tt + t) * Ll + l);
        float4 z = make_float4(nz.x * qsig.x + qmu.x, nz.y * qsig.y + qmu.y,
                               nz.z * qsig.z + qmu.z, nz.w * qsig.w + qmu.w);
        unsigned long long hi, lo;
        cvt4(z, hi, lo);
        int kg = 512 + l;
        st8b(gAg + ipos(kg, m), hi);
        st8b(gAg + ipos(kg + 1280, m), hi);
        st8b(gAg + ipos(kg + 2560, m), lo);
        st8h(aqx + qpos16(l, m), cvt4h(z));
    }
}

__device__ __forceinline__ void lstm_tail_body(int t_next) {
    __half* aqx = gAqx4[t_next & 3];
    for (int i4 = blockIdx.x * 256 + threadIdx.x; i4 < Bb * Hh / 4; i4 += REC_CTAS * 256) {
        int b = i4 >> 7;
        int n = (i4 & 127) << 2;
        const int r = b * 2048;
#define GSUM(off) ({ \
        float4 s = *(const float4*)(g_bsum + (off)); \
        _Pragma("unroll") \
        for (int sg = 0; sg < 4; sg++) { \
            float4 a = __ldcg((const float4*)(&g_gp[sg][0] + r + (off))); \
            s.x += a.x; s.y += a.y; s.z += a.z; s.w += a.w; \
        } s; })
        float4 gi = GSUM(n);
        float4 gf = GSUM(512 + n);
        float4 gg = GSUM(1024 + n);
        float4 go = GSUM(1536 + n);
#undef GSUM
        float4 co = *(const float4*)(g_c + b * 512 + n);
        float4 cn, h;
        cn.x = sigf(gf.x) * co.x + sigf(gi.x) * tanhf(gg.x);
        cn.y = sigf(gf.y) * co.y + sigf(gi.y) * tanhf(gg.y);
        cn.z = sigf(gf.z) * co.z + sigf(gi.z) * tanhf(gg.z);
        cn.w = sigf(gf.w) * co.w + sigf(gi.w) * tanhf(gg.w);
        h.x = sigf(go.x) * tanhf(cn.x);
        h.y = sigf(go.y) * tanhf(cn.y);
        h.z = sigf(go.z) * tanhf(cn.z);
        h.w = sigf(go.w) * tanhf(cn.w);
        *(float4*)(g_c + b * 512 + n) = cn;
        unsigned long long hi, lo;
        cvt4(h, hi, lo);
        int k = 512 + n;
        st8b(gApq + ipos(k, b), hi);
        st8b(gApq + ipos(k + 1024, b), hi);
        st8b(gApq + ipos(k + 2048, b), lo);
        int kg = 768 + n;
        st8b(gAg + ipos(kg, b), hi);
        st8b(gAg + ipos(kg + 1280, b), hi);
        st8b(gAg + ipos(kg + 2560, b), lo);
        st8h(aqx + qpos16(256 + n, b), cvt4h(h));
    }
    if (t_next < Tt) {
        const float* src = g_emb + (((size_t)t_next * Bb) << 9);
        for (int i4 = blockIdx.x * 256 + threadIdx.x; i4 < Bb * Ee / 4; i4 += REC_CTAS * 256) {
            int m = i4 >> 7;
            int e = (i4 & 127) << 2;
            float4 v = *(const float4*)(src + ((size_t)m << 9) + e);
            unsigned long long hi, lo;
            cvt4(v, hi, lo);
            st8b(gApq + ipos(e, m), hi);
            st8b(gApq + ipos(e + 1024, m), hi);
            st8b(gApq + ipos(e + 2048, m), lo);
            st8b(gAg + ipos(e, m), hi);
            st8b(gAg + ipos(e + 1280, m), hi);
            st8b(gAg + ipos(e + 2560, m), lo);
        }
    }
}

// ---------------- prologue: gates GEMM + LSTM tail (t=0 images) ----------------
__global__ void __launch_bounds__(256) prolog_kernel() {
    int seg = blockIdx.x >> 4, tile = blockIdx.x & 15;
    gemm_body(gAg + (size_t)seg * 15 * 8192,
              gBg + ((size_t)tile * NCH_G + seg * 15) * 8192,
              15, g_gp[seg], 2048, tile << 7);
    grid_barrier<REC_CTAS>(&g_ctrP);
    lstm_tail_body(0);
}

// ---------------- fused per-step recurrence kernel (64 CTAs) ----------------
__global__ void __launch_bounds__(256) rec_step_kernel(const float* __restrict__ noise,
                                                       float* __restrict__ out, int t) {
    {
        int seg = blockIdx.x >> 3, tile = blockIdx.x & 7;
        gemm_body(gApq + (size_t)seg * 6 * 8192,
                  gBpq + ((size_t)tile * NCH_PQ + seg * 6) * 8192,
                  6, g_pqp[seg], 1024, tile << 7);
    }
    grid_barrier<REC_CTAS>(&g_bar2[t][0]);
    z_tail_body(noise, out, t);
    signal_wait<REC_CTAS>(&g_flagZ[t]);   // barrier + producer signal for qx_persist
    {
        int seg = blockIdx.x >> 4, tile = blockIdx.x & 15;
        gemm_body(gAg + (size_t)seg * 15 * 8192,
                  gBg + ((size_t)tile * NCH_G + seg * 15) * 8192,
                  15, g_gp[seg], 2048, tile << 7);
    }
    grid_barrier<REC_CTAS>(&g_bar2[t][1]);
    // lstm_tail(t+1) writes qx A-buffer (t+1)&3, last read by qx(t-3)
    if (t >= 3) wait_count(&g_flagQ[t - 3], QX_CTAS);
    lstm_tail_body(t + 1);
}

// ---------------- persistent qx GEMM + log-softmax (84 CTAs, fp16, 3-stage) ----------------
#define STAGE_A16 (128 * PITCH)             // 18432
#define QSTG ((128 + 192) * PITCH)          // 46080
#define SMQX (3 * QSTG)                     // 138240

__device__ __forceinline__ void load_stage_qx(uint32_t st, const char* srcA, const char* srcB,
                                              int tid) {
#pragma unroll
    for (int j = 0; j < 4; j++) {
        int i = tid + j * 256;
        cpasync16(st + (i >> 3) * PITCH + (i & 7) * 16, srcA + i * 16);
    }
#pragma unroll
    for (int j = 0; j < 6; j++) {
        int i = tid + j * 256;
        cpasync16(st + STAGE_A16 + (i >> 3) * PITCH + (i & 7) * 16, srcB + i * 16);
    }
    asm volatile("cp.async.commit_group;" ::: "memory");
}

// log-softmax over one row (256 threads)
__device__ void softmax_row(float* __restrict__ x) {
    __shared__ float sred[8];
    __shared__ float sval;
    const int tid = threadIdx.x;
    float m = -3.4e38f;
    for (int i = tid; i < Vv; i += 256) m = fmaxf(m, x[i]);
#pragma unroll
    for (int o = 16; o; o >>= 1) m = fmaxf(m, __shfl_xor_sync(0xffffffffu, m, o));
    if ((tid & 31) == 0) sred[tid >> 5] = m;
    __syncthreads();
    if (tid < 32) {
        float v = (tid < 8) ? sred[tid] : -3.4e38f;
#pragma unroll
        for (int o = 4; o; o >>= 1) v = fmaxf(v, __shfl_xor_sync(0xffffffffu, v, o));
        if (tid == 0) sval = v;
    }
    __syncthreads();
    m = sval;
    float s = 0.0f;
    for (int i = tid; i < Vv; i += 256) s += expf(x[i] - m);
#pragma unroll
    for (int o = 16; o; o >>= 1) s += __shfl_xor_sync(0xffffffffu, s, o);
    __syncthreads();
    if ((tid & 31) == 0) sred[tid >> 5] = s;
    __syncthreads();
    if (tid < 32) {
        float v = (tid < 8) ? sred[tid] : 0.0f;
#pragma unroll
        for (int o = 4; o; o >>= 1) v += __shfl_xor_sync(0xffffffffu, v, o);
        if (tid == 0) sval = m + logf(v);
    }
    __syncthreads();
    float lz = sval;
    for (int i = tid; i < Vv; i += 256) x[i] -= lz;
    __syncthreads();
}

__global__ void __launch_bounds__(256) qx_persist_kernel(const float* __restrict__ qx_b,
                                                         float* __restrict__ out) {
    extern __shared__ __align__(16) char smem[];
    const uint32_t sb = s2u(smem);
    const int tid = threadIdx.x;
    const int wid = tid >> 5;
    const int lane = tid & 31;
    const int warp_m = wid >> 2;
    const int warp_n = wid & 3;
    const int n0 = blockIdx.x * QROWS;

    const char* gB = (const char*)(gBqx + (size_t)blockIdx.x * (QCH * QROWS * 64));

    const int a_row = lane & 15;
    const int a_coff = (lane >> 4) << 4;
    const int b_row = ((lane >> 4) << 3) | (lane & 7);
    const int b_coff = ((lane >> 3) & 1) << 4;
    const int g = lane >> 2, tq = lane & 3;

    for (int t = 0; t < Tt; t++) {
        wait_count(&g_flagZ[t], REC_CTAS);

        float* dst = out + OFF_QX + (size_t)t * Bb * Vv;
        const char* gA = (const char*)gAqx4[t & 3];

        float acc[4][6][4];
#pragma unroll
        for (int i = 0; i < 4; i++)
#pragma unroll
            for (int j = 0; j < 6; j++)
#pragma unroll
                for (int q = 0; q < 4; q++) acc[i][j][q] = 0.0f;

#pragma unroll
        for (int s = 0; s < 3; s++)
            load_stage_qx(sb + s * QSTG, gA + (size_t)s * 16384, gB + (size_t)s * 24576, tid);

        int slot = 0;
        for (int c = 0; c < QCH; c++) {
            asm volatile("cp.async.wait_group 2;" ::: "memory");
            __syncthreads();

            const uint32_t As = sb + slot * QSTG;
            const uint32_t Bs = As + STAGE_A16;
#pragma unroll
            for (int ks = 0; ks < 4; ks++) {
                uint32_t a[4][4];
#pragma unroll
                for (int mi = 0; mi < 4; mi++)
                    ldmatrix_x4(a[mi], As + (uint32_t)(warp_m * 64 + mi * 16 + a_row) * PITCH +
                                        ks * 32 + a_coff);
#pragma unroll
                for (int jp = 0; jp < 3; jp++) {
                    uint32_t b[4];
                    ldmatrix_x4(b, Bs + (uint32_t)(warp_n * 48 + jp * 16 + b_row) * PITCH +
                                    ks * 32 + b_coff);
#pragma unroll
                    for (int mi = 0; mi < 4; mi++) {
                        mma_f16(acc[mi][jp * 2 + 0], a[mi], b[0], b[1]);
                        mma_f16(acc[mi][jp * 2 + 1], a[mi], b[2], b[3]);
                    }
                }
            }
            __syncthreads();
            if (c + 3 < QCH)
                load_stage_qx(sb + slot * QSTG, gA + (size_t)(c + 3) * 16384,
                              gB + (size_t)(c + 3) * 24576, tid);
            else
                asm volatile("cp.async.commit_group;" ::: "memory");
            slot = (slot == 2) ? 0 : slot + 1;
        }

#pragma unroll
        for (int mi = 0; mi < 4; mi++) {
            int row = warp_m * 64 + mi * 16 + g;
#pragma unroll
            for (int nj = 0; nj < 6; nj++) {
                int col = n0 + warp_n * 48 + nj * 8 + 2 * tq;
                if (col >= Vv) continue;
                float b0 = qx_b[col], b1 = qx_b[col + 1];
                *(float2*)(dst + (size_t)row * Vv + col) =
                    make_float2(acc[mi][nj][0] + b0, acc[mi][nj][1] + b1);
                *(float2*)(dst + (size_t)(row + 8) * Vv + col) =
                    make_float2(acc[mi][nj][2] + b0, acc[mi][nj][3] + b1);
            }
        }

        // GEMM done: signal rec (A-buffer free) + all-84 barrier for softmax
        signal_wait<QX_CTAS>(&g_flagQ[t]);
        softmax_row(dst + (size_t)blockIdx.x * Vv);
        if (blockIdx.x + QX_CTAS < Bb)
            softmax_row(dst + (size_t)(blockIdx.x + QX_CTAS) * Vv);
    }
}

extern "C" void kernel_launch(void* const* d_in, const int* in_sizes, int n_in,
                              void* d_out, int out_size) {
    const float* features = (const float*)d_in[0];
    const int* captions = (const int*)d_in[1];
    const float* noise   = (const float*)d_in[3];
    const float* embed_W = (const float*)d_in[4];
    const float* W_ih    = (const float*)d_in[5];
    const float* W_hh    = (const float*)d_in[6];
    const float* b_ih    = (const float*)d_in[7];
    const float* b_hh    = (const float*)d_in[8];
    const float* qz_W    = (const float*)d_in[9];
    const float* qz_b    = (const float*)d_in[10];
    const float* prior_W = (const float*)d_in[11];
    const float* prior_b = (const float*)d_in[12];
    const float* qx_W    = (const float*)d_in[13];
    const float* qx_b    = (const float*)d_in[14];
    float* out = (float*)d_out;

    static cudaStream_t s1 = nullptr, s2 = nullptr;
    static cudaEvent_t evF = nullptr, evW = nullptr, evJ1 = nullptr;
    if (s1 == nullptr) {
        cudaStreamCreateWithFlags(&s1, cudaStreamNonBlocking);
        cudaStreamCreateWithFlags(&s2, cudaStreamNonBlocking);
        cudaEventCreateWithFlags(&evF, cudaEventDisableTiming);
        cudaEventCreateWithFlags(&evW, cudaEventDisableTiming);
        cudaEventCreateWithFlags(&evJ1, cudaEventDisableTiming);
    }

    cudaFuncSetAttribute(prolog_kernel, cudaFuncAttributeMaxDynamicSharedMemorySize, SM128);
    cudaFuncSetAttribute(rec_step_kernel, cudaFuncAttributeMaxDynamicSharedMemorySize, SM128);
    cudaFuncSetAttribute(qx_persist_kernel, cudaFuncAttributeMaxDynamicSharedMemorySize, SMQX);

    // one-time prep — fork side streams from the capture stream via an event
    prep_misc_kernel<<<(PREP_MISC_TOT + 255) / 256, 256>>>(b_ih, b_hh, qz_b, prior_b,
                                                           embed_W, captions);
    cudaEventRecord(evF, 0);
    cudaStreamWaitEvent(s1, evF, 0);
    cudaStreamWaitEvent(s2, evF, 0);
    prep_wqx_kernel<<<(16128 * 192 + 255) / 256, 256, 0, s1>>>(qx_W);
    prep_wg_kernel<<<(2048 * 320 + 255) / 256, 256, 0, s2>>>(W_ih, W_hh);
    prep_wpq_kernel<<<(1024 * 256 + 255) / 256, 256>>>(qz_W, prior_W);
    cudaEventRecord(evW, s2);
    cudaStreamWaitEvent(0, evW, 0);   // gBg ready before prolog on stream 0

    // persistent qx worker (spins on flagZ; launch on s1 after its weight prep)
    qx_persist_kernel<<<QX_CTAS, 256, SMQX, s1>>>(qx_b, out);

    // initial LSTM step: features through the gates tc path (z,h image sections are zero)
    build_feat_kernel<<<32, 512>>>(features);
    prolog_kernel<<<REC_CTAS, 256, SM128>>>();

    for (int t = 0; t < Tt; t++)
        rec_step_kernel<<<REC_CTAS, 256, SM128>>>(noise, out, t);

    // join: wait for the persistent qx kernel
    cudaEventRecord(evJ1, s1);
    cudaStreamWaitEvent(0, evJ1, 0);
}